// round 15
// baseline (speedup 1.0000x reference)
#include <cuda_runtime.h>

#define BATCH 256
#define TSTEPS 64

typedef unsigned long long u64;

// ---------------- persistent state (device globals; no allocation) ----------
__device__ float g_c1[(size_t)TSTEPS*BATCH*20*576];  // conv1+bias, all timesteps
__device__ float g_v0[BATCH*20*576];
__device__ float g_i0[BATCH*20*576];
__device__ float g_v1[BATCH*64*64];       // [b][pos(8x8)][co padded to 64]
__device__ float g_i1[BATCH*64*64];
__device__ float g_v2[BATCH*512];         // [b][m padded to 512]
__device__ float g_i2[BATCH*512];
__device__ float g_vo[BATCH*10];
__device__ float g_io[BATCH*10];
__device__ long long g_w2ll[512*64];      // conv2 w * 2^52, [t pad 512][co pad 64]
__device__ long long g_wfcll[800*512];    // fc w * 2^52, [k][m pad 512]
__device__ long long g_woutll[10*500];    // w_out * 2^52
// conv2 BYTE tables, split-precision, lane-pair packed:
//   hi: int2 {hi(co=lane), hi(co=lane+25)} at grid 2^-22
//   lo: packed short2 {lo, lo} at grid 2^-37  (entry = hi*2^-22 + lo*2^-37 +- 2^-38)
__device__ int2 g_tb2p[64*256*32];        // 4.2 MB
__device__ int  g_tb2q[64*256*32];        // 2.1 MB
__device__ long long g_tbf[200*16*512];   // fc NIBBLE table (exact int64); 13.1 MB

#define LIF_BETA 0.1f
#define LIF_IDEC 0.8f
#define LIF_VTH  1.0f

#define SCALE52_F 4503599627370496.0f     // 2^52
#define INV52_D   2.220446049250313e-16   // 2^-52

// ---------------- packed f32x2 helpers (each = two independent IEEE f32 ops) -
__device__ __forceinline__ u64 pk2(float lo, float hi) {
    u64 r; asm("mov.b64 %0, {%1, %2};" : "=l"(r) : "f"(lo), "f"(hi)); return r;
}
__device__ __forceinline__ void upk2(u64 v, float& lo, float& hi) {
    asm("mov.b64 {%0, %1}, %2;" : "=f"(lo), "=f"(hi) : "l"(v));
}
__device__ __forceinline__ u64 add2(u64 a, u64 b) {
    u64 r; asm("add.rn.f32x2 %0, %1, %2;" : "=l"(r) : "l"(a), "l"(b)); return r;
}
__device__ __forceinline__ u64 fma2(u64 a, u64 b, u64 c) {
    u64 r; asm("fma.rn.f32x2 %0, %1, %2, %3;" : "=l"(r) : "l"(a), "l"(b), "l"(c)); return r;
}

// LIF update with STRICT per-op rounding (no FMA contraction):
__device__ __forceinline__ void lif_update(float& v, float& i, float inp, float& z)
{
    float vd = __fadd_rn(v, __fmul_rn(LIF_BETA, __fsub_rn(i, v)));
    z = (vd > LIF_VTH) ? 1.f : 0.f;
    v = __fmul_rn(__fsub_rn(1.f, z), vd);
    i = __fadd_rn(__fmul_rn(LIF_IDEC, i), inp);
}

__device__ __forceinline__ float fx2f(long long acc)
{
    return (float)((double)acc * INV52_D);
}

// Recombine split accumulators (hi grid 2^-22, lo grid 2^-37) -> f32, no fp64.
// T = acch*2^15 + accl (units 2^-37), |T| < 2^43; split into exact <2^24 parts.
__device__ __forceinline__ float split_final(int acch, int accl)
{
    long long T = ((long long)acch << 15) + (long long)accl;
    int thi = (int)(T >> 24);                 // |thi| <= 2^19: exact in f32
    int tlo = (int)(T & 0xFFFFFF);            // [0,2^24): exact in f32
    return __fmaf_rn((float)thi, 1.220703125e-4f,              // 2^-13
                     __fmul_rn((float)tlo, 7.2759576141834259e-12f)); // 2^-37
}

// ---------------- setup kernels ---------------------------------------------
__global__ void zero_states() {
    int i = blockIdx.x * blockDim.x + threadIdx.x;
    if (i < BATCH*20*576) { g_v0[i] = 0.f; g_i0[i] = 0.f; }
    if (i < BATCH*64*64)  { g_v1[i] = 0.f; g_i1[i] = 0.f; }
    if (i < BATCH*512)    { g_v2[i] = 0.f; g_i2[i] = 0.f; }
    if (i < BATCH*10)     { g_vo[i] = 0.f; g_io[i] = 0.f; }
}

__global__ void prep_weights(const float* __restrict__ w2,
                             const float* __restrict__ w_fc,
                             const float* __restrict__ w_out) {
    int i = blockIdx.x * blockDim.x + threadIdx.x;
    if (i < 512*64) {                 // conv2: [t][co], t = ci*25+k
        int t = i >> 6, co = i & 63;
        float w = (t < 500 && co < 50) ? w2[co*500 + t] : 0.f;
        g_w2ll[i] = __float2ll_rn(__fmul_rn(w, SCALE52_F));
    }
    if (i < 800*512) {                // fc transpose: [k][m]
        int k = i >> 9, m = i & 511;
        float w = (m < 500) ? w_fc[m*800 + k] : 0.f;
        g_wfcll[i] = __float2ll_rn(__fmul_rn(w, SCALE52_F));
    }
    if (i < 10*500) {
        g_woutll[i] = __float2ll_rn(__fmul_rn(w_out[i], SCALE52_F));
    }
}

// Build partial-sum tables. conv2: exact int64 byte-group sum split into
// hi (grid 2^-22) + lo (grid 2^-37), residual <= 2^-38 per entry.
// fc: exact int64 nibble sums (bit-identical accumulation).
__global__ void prep_tables() {
    int i = blockIdx.x * blockDim.x + threadIdx.x;
    if (i < 64*256*32) {              // conv2 byte table, lane-pair packed
        int lane = i & 31, idx = (i >> 5) & 255, g = i >> 13;
        int hi0 = 0, hi1 = 0, lo0 = 0, lo1 = 0;
        if (lane < 25) {
#pragma unroll
            for (int bank = 0; bank < 2; bank++) {
                int co = lane + bank*25;      // co in [0,50)
                long long S = 0;
#pragma unroll
                for (int j = 0; j < 8; j++)
                    if ((idx >> j) & 1) S += g_w2ll[(8*g + j)*64 + co];
                int hi = (int)((S + (1LL << 29)) >> 30);            // grid 2^-22
                int lo = (int)((S - ((long long)hi << 30) + (1 << 14)) >> 15); // 2^-37
                if (bank == 0) { hi0 = hi; lo0 = lo; }
                else           { hi1 = hi; lo1 = lo; }
            }
        }
        g_tb2p[i] = make_int2(hi0, hi1);
        g_tb2q[i] = (lo0 & 0xFFFF) | (lo1 << 16);
    }
    if (i < 200*16*512) {             // fc nibble table
        int m = i & 511, idx = (i >> 9) & 15, gg = i >> 13;
        long long s = 0;
#pragma unroll
        for (int j = 0; j < 4; j++)
            if ((idx >> j) & 1) s += g_wfcll[(4*gg + j)*512 + m];
        g_tbf[i] = s;
    }
}

// ---------------- K1: conv1 for ALL timesteps (state-independent) -----------
// grid (B*T, 20), block 160. Thread = one pooled quad; packed f32x2 fused limb
// accumulation (5 fma-pipe ops / 2 products; deviation ~1e-12 from exact).
__global__ __launch_bounds__(160) void k_conv1_all(
    const float* __restrict__ x, const float* __restrict__ w1,
    const float* __restrict__ b1)
{
    __shared__ float sx[784];
    __shared__ float sw[25];
    int tb = blockIdx.x;              // t*BATCH + b
    int cch = blockIdx.y;
    int tid = threadIdx.x;
    const float* xp = x + (size_t)tb * 784;
    for (int i = tid; i < 784; i += 160) sx[i] = xp[i];
    if (tid < 25) sw[tid] = w1[cch*25 + tid];
    __syncthreads();
    if (tid >= 144) return;

    int yp = tid / 12, xq = tid % 12;
    int y0 = 2*yp, x0 = 2*xq;

    float in[6][6];
#pragma unroll
    for (int i = 0; i < 6; i++)
#pragma unroll
        for (int j = 0; j < 6; j++)
            in[i][j] = sx[(y0+i)*28 + x0 + j];

    const u64 SGN  = 0x8000000080000000ULL;
    const u64 M18  = pk2(48.0f, 48.0f);            // 1.5*2^5 -> grid 2^-18
    const u64 nM18 = pk2(-48.0f, -48.0f);

    u64 AhT = 0, FrT = 0;                          // top row (a00,a01)
    u64 AhB = 0, FrB = 0;                          // bottom row (a10,a11)

#pragma unroll
    for (int ki = 0; ki < 5; ki++)
#pragma unroll
        for (int kj = 0; kj < 5; kj++) {
            float w = sw[ki*5 + kj];
            u64 ww = pk2(w, w);
            u64 aT = pk2(in[ki  ][kj], in[ki  ][kj+1]);
            u64 aB = pk2(in[ki+1][kj], in[ki+1][kj+1]);
            {
                u64 t1 = fma2(aT, ww, M18);
                u64 hf = add2(t1, nM18);
                AhT = add2(AhT, hf);
                u64 r  = fma2(aT, ww, hf ^ SGN);
                FrT = add2(FrT, r);
            }
            {
                u64 t1 = fma2(aB, ww, M18);
                u64 hf = add2(t1, nM18);
                AhB = add2(AhB, hf);
                u64 r  = fma2(aB, ww, hf ^ SGN);
                FrB = add2(FrB, r);
            }
        }

    float bias = __ldg(&b1[cch]);
    float ah0, ah1, fr0, fr1;
    float s00, s01, s10, s11;

    upk2(AhT, ah0, ah1); upk2(FrT, fr0, fr1);
    s00 = __fadd_rn(__fadd_rn(ah0, fr0), bias);
    s01 = __fadd_rn(__fadd_rn(ah1, fr1), bias);
    upk2(AhB, ah0, ah1); upk2(FrB, fr0, fr1);
    s10 = __fadd_rn(__fadd_rn(ah0, fr0), bias);
    s11 = __fadd_rn(__fadd_rn(ah1, fr1), bias);

    float* outp = g_c1 + ((size_t)tb*20 + cch)*576;
    *(float2*)&outp[(y0  )*24 + x0] = make_float2(s00, s01);
    *(float2*)&outp[(y0+1)*24 + x0] = make_float2(s10, s11);
}

// ---------------- K2: ALL 64 timesteps, persistent (samples independent) ----
// grid 128, block 1024 = two independent 512-thread halves (one sample each),
// synced by named barriers. Conv2: split-precision byte tables (lanes 0-24 own
// channel pair (lane, lane+25)); FC: exact int64 nibble tables.
__global__ __launch_bounds__(1024) void k_steps(
    const float* __restrict__ b2, const float* __restrict__ b_fc,
    float* __restrict__ volt)
{
    __shared__ float s_in[2][2880];
    __shared__ int   s_off[512];
    __shared__ float s_sp1[2][800];
    __shared__ float s_z2[2][512];

    int half = threadIdx.x >> 9;
    int tid  = threadIdx.x & 511;
    int b    = blockIdx.x*2 + half;
    int lane = tid & 31;
    int warp = tid >> 5;              // 0..15 within half
    int barid = 1 + half;

    if (threadIdx.x < 512) {
        int tt = (threadIdx.x < 500) ? (int)threadIdx.x : 0;
        int ci = tt / 25, k = tt % 25;
        s_off[threadIdx.x] = ci*144 + (k/5)*12 + (k%5);
    }

    int yp = warp >> 2, xq = warp & 3;
    bool own = (lane < 25);
    int co = lane, co2 = lane + 25;   // owned channel pair (lane<25)
    float bias0 = own ? __ldg(&b2[co])  : 0.f;
    float bias1 = own ? __ldg(&b2[co2]) : 0.f;
    float biasf = (tid < 500) ? __ldg(&b_fc[tid]) : 0.f;
    float* v0p = g_v0 + b*11520;
    float* i0p = g_i0 + b*11520;

    __syncthreads();                  // s_off visible to both halves

    for (int t = 0; t < TSTEPS; t++) {
        // ---- Phase A: LIF0 + pool ----
        {
            const float* c1 = g_c1 + ((size_t)t*BATCH + b)*11520;
            for (int q = tid; q < 2880; q += 512) {
                int c = q / 144, rr = q % 144;
                int r = rr / 12, xx = rr % 12;
                int base = (c*24 + 2*r)*24 + 2*xx;
                float zmax = 0.f;
#pragma unroll
                for (int dy = 0; dy < 2; dy++) {
                    int idx = base + dy*24;
                    float2 inp = *(const float2*)&c1[idx];
                    float2 v  = *(float2*)&v0p[idx];
                    float2 ii = *(float2*)&i0p[idx];
                    float z0, z1;
                    lif_update(v.x, ii.x, inp.x, z0);
                    lif_update(v.y, ii.y, inp.y, z1);
                    *(float2*)&v0p[idx] = v;
                    *(float2*)&i0p[idx] = ii;
                    zmax = fmaxf(zmax, fmaxf(z0, z1));
                }
                s_in[half][q] = zmax;
            }
        }
        asm volatile("bar.sync %0, 512;" :: "r"(barid) : "memory");

        // ---- Phase B: conv2 + LIF1 + pool (split byte tables) ----
        {
            float z0max = 0.f, z1max = 0.f;
#pragma unroll
            for (int sp = 0; sp < 4; sp++) {
                int dy = sp >> 1, dx = sp & 1;
                int y = 2*yp + dy, x = 2*xq + dx;
                int base = y*12 + x;

                int acch0 = 0, accl0 = 0, acch1 = 0, accl1 = 0;
#pragma unroll 1
                for (int ch = 0; ch < 16; ch++) {
                    float a = s_in[half][s_off[ch*32 + lane] + base];
                    unsigned msk = __ballot_sync(0xffffffffu, a != 0.f);
#pragma unroll
                    for (int j = 0; j < 4; j++) {
                        unsigned idx = (msk >> (8*j)) & 255u;
                        if (idx && own) {
                            int off = ((ch*4 + j)*256 + (int)idx)*32 + lane;
                            int2 hv = __ldg(&g_tb2p[off]);
                            int  pk = __ldg(&g_tb2q[off]);
                            acch0 += hv.x;
                            acch1 += hv.y;
                            accl0 += (pk << 16) >> 16;
                            accl1 += pk >> 16;
                        }
                    }
                }
                if (own) {
                    float s0 = split_final(acch0, accl0);
                    float s1 = split_final(acch1, accl1);
                    float inp0 = __fmul_rn(10.0f, __fadd_rn(s0, bias0));
                    float inp1 = __fmul_rn(10.0f, __fadd_rn(s1, bias1));

                    int sidx = (b*64 + y*8 + x)*64 + lane;
                    float v0 = g_v1[sidx],      i0 = g_i1[sidx];
                    float v1 = g_v1[sidx + 25], i1 = g_i1[sidx + 25];
                    float z0, z1;
                    lif_update(v0, i0, inp0, z0);
                    lif_update(v1, i1, inp1, z1);
                    g_v1[sidx] = v0;      g_i1[sidx] = i0;
                    g_v1[sidx + 25] = v1; g_i1[sidx + 25] = i1;
                    z0max = fmaxf(z0max, z0);
                    z1max = fmaxf(z1max, z1);
                }
            }
            if (own) {
                int pos = yp*4 + xq;
                s_sp1[half][co*16 + pos]  = z0max;
                s_sp1[half][co2*16 + pos] = z1max;
            }
        }
        asm volatile("bar.sync %0, 512;" :: "r"(barid) : "memory");

        // ---- Phase C: FC + LIF2 (nibble tables, exact int64) ----
        {
            int m = tid;
            long long acc = 0;
#pragma unroll 1
            for (int ch = 0; ch < 25; ch++) {
                float a = s_sp1[half][ch*32 + lane];
                unsigned msk = __ballot_sync(0xffffffffu, a != 0.f);
#pragma unroll
                for (int j = 0; j < 8; j++) {
                    unsigned idx = (msk >> (4*j)) & 15u;
                    if (idx)
                        acc += __ldg(&g_tbf[((ch*8 + j)*16 + idx)*512 + m]);
                }
            }
            float inp = __fadd_rn(fx2f(acc), biasf);

            int sidx = b*512 + m;
            float v = g_v2[sidx], ii = g_i2[sidx];
            float z;
            lif_update(v, ii, inp, z);
            g_v2[sidx] = v;
            g_i2[sidx] = ii;
            s_z2[half][m] = (m < 500) ? z : 0.f;
        }
        asm volatile("bar.sync %0, 512;" :: "r"(barid) : "memory");

        // ---- Phase D: readout + LI ----
        if (warp < 10) {
            long long ao = 0;
            const long long* wr = g_woutll + warp*500;
#pragma unroll 1
            for (int j = lane; j < 500; j += 32)
                if (s_z2[half][j] != 0.f) ao += __ldg(wr + j);
#pragma unroll
            for (int off = 16; off; off >>= 1)
                ao += __shfl_xor_sync(0xffffffffu, ao, off);
            if (lane == 0) {
                float sum = fx2f(ao);
                int idx = b*10 + warp;
                float vo = g_vo[idx], io = g_io[idx];
                float vn = __fadd_rn(vo, __fmul_rn(LIF_BETA, __fsub_rn(io, vo)));
                g_vo[idx] = vn;
                g_io[idx] = __fadd_rn(__fmul_rn(LIF_IDEC, io), sum);
                volt[((size_t)t * BATCH + b)*10 + warp] = vn;
            }
        }
        asm volatile("bar.sync %0, 512;" :: "r"(barid) : "memory");
    }
}

// ---------------- launch (single stream, serial — R13 structure) ------------
extern "C" void kernel_launch(void* const* d_in, const int* in_sizes, int n_in,
                              void* d_out, int out_size)
{
    const float* x     = (const float*)d_in[0];
    const float* w1    = (const float*)d_in[1];
    const float* b1    = (const float*)d_in[2];
    const float* w2    = (const float*)d_in[3];
    const float* b2    = (const float*)d_in[4];
    const float* w_fc  = (const float*)d_in[5];
    const float* b_fc  = (const float*)d_in[6];
    const float* w_out = (const float*)d_in[7];
    float* volt = (float*)d_out;

    zero_states<<<(BATCH*20*576 + 255)/256, 256>>>();
    prep_weights<<<(800*512 + 255)/256, 256>>>(w2, w_fc, w_out);
    prep_tables<<<(200*16*512 + 255)/256, 256>>>();

    dim3 gc1(BATCH*TSTEPS, 20);
    k_conv1_all<<<gc1, 160>>>(x, w1, b1);

    k_steps<<<BATCH/2, 1024>>>(b2, b_fc, volt);
}

// round 16
// speedup vs baseline: 1.0809x; 1.0809x over previous
#include <cuda_runtime.h>

#define BATCH 256
#define TSTEPS 64

typedef unsigned long long u64;

// ---------------- persistent state (device globals; no allocation) ----------
__device__ float g_c1[(size_t)TSTEPS*BATCH*20*576];  // conv1+bias, all timesteps
__device__ float g_v1[BATCH*64*64];       // [b][pos(8x8)][co padded to 64]
__device__ float g_i1[BATCH*64*64];
__device__ float g_v2[BATCH*512];         // [b][m padded to 512]
__device__ float g_i2[BATCH*512];
__device__ float g_vo[BATCH*10];
__device__ float g_io[BATCH*10];
__device__ long long g_w2ll[512*64];      // conv2 w * 2^52, [t pad 512][co pad 64]
__device__ long long g_wfcll[800*512];    // fc w * 2^52, [k][m pad 512]
__device__ long long g_woutll[10*500];    // w_out * 2^52
// exact int64 partial-sum tables
__device__ long long g_tb2b[64*256*64];   // conv2 BYTE table: [g][idx][lane*2+bank]; 8.4 MB
__device__ long long g_tbf[200*16*512];   // fc NIBBLE table: [gg][idx][m]; 13.1 MB

#define LIF_BETA 0.1f
#define LIF_IDEC 0.8f
#define LIF_VTH  1.0f

#define SCALE52_F 4503599627370496.0f     // 2^52
#define INV52_D   2.220446049250313e-16   // 2^-52

// dynamic smem layout for k_steps (bytes)
#define SM_VI0   0            // float2 [2][11520]  (v,i) layer-0 state
#define SM_IN    184320       // float  [2][2880]
#define SM_OFF   207360       // int    [512]
#define SM_SP1   209408       // float  [2][800]
#define SM_Z2    215808       // float  [2][512]
#define SM_TOTAL 219904

// ---------------- packed f32x2 helpers (each = two independent IEEE f32 ops) -
__device__ __forceinline__ u64 pk2(float lo, float hi) {
    u64 r; asm("mov.b64 %0, {%1, %2};" : "=l"(r) : "f"(lo), "f"(hi)); return r;
}
__device__ __forceinline__ void upk2(u64 v, float& lo, float& hi) {
    asm("mov.b64 {%0, %1}, %2;" : "=f"(lo), "=f"(hi) : "l"(v));
}
__device__ __forceinline__ u64 add2(u64 a, u64 b) {
    u64 r; asm("add.rn.f32x2 %0, %1, %2;" : "=l"(r) : "l"(a), "l"(b)); return r;
}
__device__ __forceinline__ u64 fma2(u64 a, u64 b, u64 c) {
    u64 r; asm("fma.rn.f32x2 %0, %1, %2, %3;" : "=l"(r) : "l"(a), "l"(b), "l"(c)); return r;
}

// LIF update with STRICT per-op rounding (no FMA contraction):
__device__ __forceinline__ void lif_update(float& v, float& i, float inp, float& z)
{
    float vd = __fadd_rn(v, __fmul_rn(LIF_BETA, __fsub_rn(i, v)));
    z = (vd > LIF_VTH) ? 1.f : 0.f;
    v = __fmul_rn(__fsub_rn(1.f, z), vd);
    i = __fadd_rn(__fmul_rn(LIF_IDEC, i), inp);
}

__device__ __forceinline__ float fx2f(long long acc)
{
    return (float)((double)acc * INV52_D);
}

// ---------------- setup kernels ---------------------------------------------
__global__ void zero_states() {
    int i = blockIdx.x * blockDim.x + threadIdx.x;
    if (i < BATCH*64*64)  { g_v1[i] = 0.f; g_i1[i] = 0.f; }
    if (i < BATCH*512)    { g_v2[i] = 0.f; g_i2[i] = 0.f; }
    if (i < BATCH*10)     { g_vo[i] = 0.f; g_io[i] = 0.f; }
}

__global__ void prep_weights(const float* __restrict__ w2,
                             const float* __restrict__ w_fc,
                             const float* __restrict__ w_out) {
    int i = blockIdx.x * blockDim.x + threadIdx.x;
    if (i < 512*64) {                 // conv2: [t][co], t = ci*25+k
        int t = i >> 6, co = i & 63;
        float w = (t < 500 && co < 50) ? w2[co*500 + t] : 0.f;
        g_w2ll[i] = __float2ll_rn(__fmul_rn(w, SCALE52_F));
    }
    if (i < 800*512) {                // fc transpose: [k][m]
        int k = i >> 9, m = i & 511;
        float w = (m < 500) ? w_fc[m*800 + k] : 0.f;
        g_wfcll[i] = __float2ll_rn(__fmul_rn(w, SCALE52_F));
    }
    if (i < 10*500) {
        g_woutll[i] = __float2ll_rn(__fmul_rn(w_out[i], SCALE52_F));
    }
}

// Build partial-sum tables from the exact int64 weights (associative ->
// results BIT-IDENTICAL to per-term accumulation).
__global__ void prep_tables() {
    int i = blockIdx.x * blockDim.x + threadIdx.x;
    if (i < 64*256*64) {              // conv2 byte table
        int bank = i & 1, lane = (i >> 1) & 31;
        int idx = (i >> 6) & 255, g = i >> 14;
        int co = lane + bank*32;
        long long s = 0;
#pragma unroll
        for (int j = 0; j < 8; j++)
            if ((idx >> j) & 1) s += g_w2ll[(8*g + j)*64 + co];
        g_tb2b[i] = s;
    }
    if (i < 200*16*512) {             // fc nibble table
        int m = i & 511, idx = (i >> 9) & 15, gg = i >> 13;
        long long s = 0;
#pragma unroll
        for (int j = 0; j < 4; j++)
            if ((idx >> j) & 1) s += g_wfcll[(4*gg + j)*512 + m];
        g_tbf[i] = s;
    }
}

// ---------------- K1: conv1 for ALL timesteps (state-independent) -----------
// grid (B*T, 20), block 160. Thread = one pooled quad; packed f32x2 fused limb
// accumulation (5 fma-pipe ops / 2 products; deviation ~1e-12 from exact).
__global__ __launch_bounds__(160) void k_conv1_all(
    const float* __restrict__ x, const float* __restrict__ w1,
    const float* __restrict__ b1)
{
    __shared__ float sx[784];
    __shared__ float sw[25];
    int tb = blockIdx.x;              // t*BATCH + b
    int cch = blockIdx.y;
    int tid = threadIdx.x;
    const float* xp = x + (size_t)tb * 784;
    for (int i = tid; i < 784; i += 160) sx[i] = xp[i];
    if (tid < 25) sw[tid] = w1[cch*25 + tid];
    __syncthreads();
    if (tid >= 144) return;

    int yp = tid / 12, xq = tid % 12;
    int y0 = 2*yp, x0 = 2*xq;

    float in[6][6];
#pragma unroll
    for (int i = 0; i < 6; i++)
#pragma unroll
        for (int j = 0; j < 6; j++)
            in[i][j] = sx[(y0+i)*28 + x0 + j];

    const u64 SGN  = 0x8000000080000000ULL;
    const u64 M18  = pk2(48.0f, 48.0f);            // 1.5*2^5 -> grid 2^-18
    const u64 nM18 = pk2(-48.0f, -48.0f);

    u64 AhT = 0, FrT = 0;                          // top row (a00,a01)
    u64 AhB = 0, FrB = 0;                          // bottom row (a10,a11)

#pragma unroll
    for (int ki = 0; ki < 5; ki++)
#pragma unroll
        for (int kj = 0; kj < 5; kj++) {
            float w = sw[ki*5 + kj];
            u64 ww = pk2(w, w);
            u64 aT = pk2(in[ki  ][kj], in[ki  ][kj+1]);
            u64 aB = pk2(in[ki+1][kj], in[ki+1][kj+1]);
            {
                u64 t1 = fma2(aT, ww, M18);
                u64 hf = add2(t1, nM18);
                AhT = add2(AhT, hf);
                u64 r  = fma2(aT, ww, hf ^ SGN);
                FrT = add2(FrT, r);
            }
            {
                u64 t1 = fma2(aB, ww, M18);
                u64 hf = add2(t1, nM18);
                AhB = add2(AhB, hf);
                u64 r  = fma2(aB, ww, hf ^ SGN);
                FrB = add2(FrB, r);
            }
        }

    float bias = __ldg(&b1[cch]);
    float ah0, ah1, fr0, fr1;
    float s00, s01, s10, s11;

    upk2(AhT, ah0, ah1); upk2(FrT, fr0, fr1);
    s00 = __fadd_rn(__fadd_rn(ah0, fr0), bias);
    s01 = __fadd_rn(__fadd_rn(ah1, fr1), bias);
    upk2(AhB, ah0, ah1); upk2(FrB, fr0, fr1);
    s10 = __fadd_rn(__fadd_rn(ah0, fr0), bias);
    s11 = __fadd_rn(__fadd_rn(ah1, fr1), bias);

    float* outp = g_c1 + ((size_t)tb*20 + cch)*576;
    *(float2*)&outp[(y0  )*24 + x0] = make_float2(s00, s01);
    *(float2*)&outp[(y0+1)*24 + x0] = make_float2(s10, s11);
}

// ---------------- K2: ALL 64 timesteps, persistent (samples independent) ----
// grid 128, block 1024 = two independent 512-thread halves (one sample each),
// synced by named barriers. Layer-0 LIF state (v0,i0) lives ENTIRELY in
// dynamic SMEM (interleaved float2) -> zero L2 traffic for phase A state.
// Conv2: byte tables (8 terms/load, exact int64); FC: nibble tables.
__global__ __launch_bounds__(1024) void k_steps(
    const float* __restrict__ b2, const float* __restrict__ b_fc,
    float* __restrict__ volt)
{
    extern __shared__ char smem[];
    float2* vi0  = (float2*)(smem + SM_VI0);    // [2][11520]
    float*  s_in = (float*) (smem + SM_IN);     // [2][2880]
    int*    s_off= (int*)   (smem + SM_OFF);    // [512]
    float*  s_sp1= (float*) (smem + SM_SP1);    // [2][800]
    float*  s_z2 = (float*) (smem + SM_Z2);     // [2][512]

    int half = threadIdx.x >> 9;
    int tid  = threadIdx.x & 511;
    int b    = blockIdx.x*2 + half;
    int lane = tid & 31;
    int warp = tid >> 5;              // 0..15 within half
    int barid = 1 + half;

    if (threadIdx.x < 512) {
        int tt = (threadIdx.x < 500) ? (int)threadIdx.x : 0;
        int ci = tt / 25, k = tt % 25;
        s_off[threadIdx.x] = ci*144 + (k/5)*12 + (k%5);
    }

    // zero layer-0 state in smem (deterministic per replay)
    float2* vi = vi0 + half*11520;
    for (int q = tid; q < 11520; q += 512) vi[q] = make_float2(0.f, 0.f);

    int yp = warp >> 2, xq = warp & 3;
    int co = lane, co2 = lane + 32;
    float bias0 = __ldg(&b2[co]);
    float bias1 = (co2 < 50) ? __ldg(&b2[co2]) : 0.f;
    float biasf = (tid < 500) ? __ldg(&b_fc[tid]) : 0.f;

    __syncthreads();                  // s_off + vi0 visible

    for (int t = 0; t < TSTEPS; t++) {
        // ---- Phase A: LIF0 + pool (state in smem) ----
        {
            const float* c1 = g_c1 + ((size_t)t*BATCH + b)*11520;
            for (int q = tid; q < 2880; q += 512) {
                int c = q / 144, rr = q % 144;
                int r = rr / 12, xx = rr % 12;
                int base = (c*24 + 2*r)*24 + 2*xx;
                float zmax = 0.f;
#pragma unroll
                for (int dy = 0; dy < 2; dy++) {
                    int idx = base + dy*24;
                    float2 inp = *(const float2*)&c1[idx];
                    float2 a = vi[idx];
                    float2 bv = vi[idx + 1];
                    float z0, z1;
                    lif_update(a.x,  a.y,  inp.x, z0);
                    lif_update(bv.x, bv.y, inp.y, z1);
                    vi[idx]     = a;
                    vi[idx + 1] = bv;
                    zmax = fmaxf(zmax, fmaxf(z0, z1));
                }
                s_in[half*2880 + q] = zmax;
            }
        }
        asm volatile("bar.sync %0, 512;" :: "r"(barid) : "memory");

        // ---- Phase B: conv2 + LIF1 + pool (byte tables, 8 terms/load) ----
        {
            float z0max = 0.f, z1max = 0.f;
#pragma unroll
            for (int sp = 0; sp < 4; sp++) {
                int dy = sp >> 1, dx = sp & 1;
                int y = 2*yp + dy, x = 2*xq + dx;
                int base = y*12 + x;

                long long acc0 = 0, acc1 = 0;
#pragma unroll 1
                for (int ch = 0; ch < 16; ch++) {
                    float a = s_in[half*2880 + s_off[ch*32 + lane] + base];
                    unsigned msk = __ballot_sync(0xffffffffu, a != 0.f);
#pragma unroll
                    for (int j = 0; j < 4; j++) {
                        unsigned idx = (msk >> (8*j)) & 255u;
                        if (idx) {
                            const longlong2 wv = *(const longlong2*)
                                &g_tb2b[((ch*4 + j)*256 + idx)*64 + lane*2];
                            acc0 += wv.x;
                            acc1 += wv.y;
                        }
                    }
                }
                float inp0 = __fmul_rn(10.0f, __fadd_rn(fx2f(acc0), bias0));
                float inp1 = __fmul_rn(10.0f, __fadd_rn(fx2f(acc1), bias1));

                int sidx = (b*64 + y*8 + x)*64 + lane;
                float v0 = g_v1[sidx],      i0 = g_i1[sidx];
                float v1 = g_v1[sidx + 32], i1 = g_i1[sidx + 32];
                float z0, z1;
                lif_update(v0, i0, inp0, z0);
                lif_update(v1, i1, inp1, z1);
                g_v1[sidx] = v0;      g_i1[sidx] = i0;
                g_v1[sidx + 32] = v1; g_i1[sidx + 32] = i1;
                z0max = fmaxf(z0max, z0);
                z1max = fmaxf(z1max, z1);
            }
            int pos = yp*4 + xq;
            s_sp1[half*800 + co*16 + pos] = z0max;
            if (co2 < 50) s_sp1[half*800 + co2*16 + pos] = z1max;
        }
        asm volatile("bar.sync %0, 512;" :: "r"(barid) : "memory");

        // ---- Phase C: FC + LIF2 (nibble tables) ----
        {
            int m = tid;
            long long acc = 0;
#pragma unroll 1
            for (int ch = 0; ch < 25; ch++) {
                float a = s_sp1[half*800 + ch*32 + lane];
                unsigned msk = __ballot_sync(0xffffffffu, a != 0.f);
#pragma unroll
                for (int j = 0; j < 8; j++) {
                    unsigned idx = (msk >> (4*j)) & 15u;
                    if (idx)
                        acc += __ldg(&g_tbf[((ch*8 + j)*16 + idx)*512 + m]);
                }
            }
            float inp = __fadd_rn(fx2f(acc), biasf);

            int sidx = b*512 + m;
            float v = g_v2[sidx], ii = g_i2[sidx];
            float z;
            lif_update(v, ii, inp, z);
            g_v2[sidx] = v;
            g_i2[sidx] = ii;
            s_z2[half*512 + m] = (m < 500) ? z : 0.f;
        }
        asm volatile("bar.sync %0, 512;" :: "r"(barid) : "memory");

        // ---- Phase D: readout + LI ----
        if (warp < 10) {
            long long ao = 0;
            const long long* wr = g_woutll + warp*500;
#pragma unroll 1
            for (int j = lane; j < 500; j += 32)
                if (s_z2[half*512 + j] != 0.f) ao += __ldg(wr + j);
#pragma unroll
            for (int off = 16; off; off >>= 1)
                ao += __shfl_xor_sync(0xffffffffu, ao, off);
            if (lane == 0) {
                float sum = fx2f(ao);
                int idx = b*10 + warp;
                float vo = g_vo[idx], io = g_io[idx];
                float vn = __fadd_rn(vo, __fmul_rn(LIF_BETA, __fsub_rn(io, vo)));
                g_vo[idx] = vn;
                g_io[idx] = __fadd_rn(__fmul_rn(LIF_IDEC, io), sum);
                volt[((size_t)t * BATCH + b)*10 + warp] = vn;
            }
        }
        asm volatile("bar.sync %0, 512;" :: "r"(barid) : "memory");
    }
}

// ---------------- launch (single stream, serial) -----------------------------
extern "C" void kernel_launch(void* const* d_in, const int* in_sizes, int n_in,
                              void* d_out, int out_size)
{
    const float* x     = (const float*)d_in[0];
    const float* w1    = (const float*)d_in[1];
    const float* b1    = (const float*)d_in[2];
    const float* w2    = (const float*)d_in[3];
    const float* b2    = (const float*)d_in[4];
    const float* w_fc  = (const float*)d_in[5];
    const float* b_fc  = (const float*)d_in[6];
    const float* w_out = (const float*)d_in[7];
    float* volt = (float*)d_out;

    cudaFuncSetAttribute(k_steps,
                         cudaFuncAttributeMaxDynamicSharedMemorySize, SM_TOTAL);

    zero_states<<<(BATCH*64*64 + 255)/256, 256>>>();
    prep_weights<<<(800*512 + 255)/256, 256>>>(w2, w_fc, w_out);
    prep_tables<<<(200*16*512 + 255)/256, 256>>>();

    dim3 gc1(BATCH*TSTEPS, 20);
    k_conv1_all<<<gc1, 160>>>(x, w1, b1);

    k_steps<<<BATCH/2, 1024, SM_TOTAL>>>(b2, b_fc, volt);
}

// round 17
// speedup vs baseline: 1.1745x; 1.0866x over previous
#include <cuda_runtime.h>

#define BATCH 256
#define TSTEPS 64

typedef unsigned long long u64;

// ---------------- persistent state (device globals; no allocation) ----------
__device__ float g_v0[BATCH*20*576];
__device__ float g_i0[BATCH*20*576];
__device__ float g_v1[BATCH*64*64];       // [b][pos(8x8)][co padded to 64]
__device__ float g_i1[BATCH*64*64];
__device__ float g_v2[BATCH*512];         // [b][m padded to 512]
__device__ float g_i2[BATCH*512];
__device__ float g_vo[BATCH*10];
__device__ float g_io[BATCH*10];
__device__ long long g_w2ll[512*64];      // conv2 w * 2^52, [t pad 512][co pad 64]
__device__ long long g_wfcll[800*512];    // fc w * 2^52, [k][m pad 512]
__device__ long long g_woutll[10*500];    // w_out * 2^52
// exact int64 partial-sum tables
__device__ long long g_tb2b[64*256*64];   // conv2 BYTE table: [g][idx][lane*2+bank]; 8.4 MB
__device__ long long g_tbf[200*16*512];   // fc NIBBLE table: [gg][idx][m]; 13.1 MB

#define LIF_BETA 0.1f
#define LIF_IDEC 0.8f
#define LIF_VTH  1.0f

#define SCALE52_F 4503599627370496.0f     // 2^52
#define INV52_D   2.220446049250313e-16   // 2^-52

// ---------------- packed f32x2 helpers (each = two independent IEEE f32 ops) -
__device__ __forceinline__ u64 pk2(float lo, float hi) {
    u64 r; asm("mov.b64 %0, {%1, %2};" : "=l"(r) : "f"(lo), "f"(hi)); return r;
}
__device__ __forceinline__ void upk2(u64 v, float& lo, float& hi) {
    asm("mov.b64 {%0, %1}, %2;" : "=f"(lo), "=f"(hi) : "l"(v));
}
__device__ __forceinline__ u64 add2(u64 a, u64 b) {
    u64 r; asm("add.rn.f32x2 %0, %1, %2;" : "=l"(r) : "l"(a), "l"(b)); return r;
}
__device__ __forceinline__ u64 fma2(u64 a, u64 b, u64 c) {
    u64 r; asm("fma.rn.f32x2 %0, %1, %2, %3;" : "=l"(r) : "l"(a), "l"(b), "l"(c)); return r;
}

// LIF update with STRICT per-op rounding (no FMA contraction):
__device__ __forceinline__ void lif_update(float& v, float& i, float inp, float& z)
{
    float vd = __fadd_rn(v, __fmul_rn(LIF_BETA, __fsub_rn(i, v)));
    z = (vd > LIF_VTH) ? 1.f : 0.f;
    v = __fmul_rn(__fsub_rn(1.f, z), vd);
    i = __fadd_rn(__fmul_rn(LIF_IDEC, i), inp);
}

__device__ __forceinline__ float fx2f(long long acc)
{
    return (float)((double)acc * INV52_D);
}

// ---------------- setup kernels ---------------------------------------------
__global__ void zero_states() {
    int i = blockIdx.x * blockDim.x + threadIdx.x;
    if (i < BATCH*20*576) { g_v0[i] = 0.f; g_i0[i] = 0.f; }
    if (i < BATCH*64*64)  { g_v1[i] = 0.f; g_i1[i] = 0.f; }
    if (i < BATCH*512)    { g_v2[i] = 0.f; g_i2[i] = 0.f; }
    if (i < BATCH*10)     { g_vo[i] = 0.f; g_io[i] = 0.f; }
}

__global__ void prep_weights(const float* __restrict__ w2,
                             const float* __restrict__ w_fc,
                             const float* __restrict__ w_out) {
    int i = blockIdx.x * blockDim.x + threadIdx.x;
    if (i < 512*64) {                 // conv2: [t][co], t = ci*25+k
        int t = i >> 6, co = i & 63;
        float w = (t < 500 && co < 50) ? w2[co*500 + t] : 0.f;
        g_w2ll[i] = __float2ll_rn(__fmul_rn(w, SCALE52_F));
    }
    if (i < 800*512) {                // fc transpose: [k][m]
        int k = i >> 9, m = i & 511;
        float w = (m < 500) ? w_fc[m*800 + k] : 0.f;
        g_wfcll[i] = __float2ll_rn(__fmul_rn(w, SCALE52_F));
    }
    if (i < 10*500) {
        g_woutll[i] = __float2ll_rn(__fmul_rn(w_out[i], SCALE52_F));
    }
}

// Build partial-sum tables from the exact int64 weights (associative ->
// results BIT-IDENTICAL to per-term accumulation).
__global__ void prep_tables() {
    int i = blockIdx.x * blockDim.x + threadIdx.x;
    if (i < 64*256*64) {              // conv2 byte table
        int bank = i & 1, lane = (i >> 1) & 31;
        int idx = (i >> 6) & 255, g = i >> 14;
        int co = lane + bank*32;
        long long s = 0;
#pragma unroll
        for (int j = 0; j < 8; j++)
            if ((idx >> j) & 1) s += g_w2ll[(8*g + j)*64 + co];
        g_tb2b[i] = s;
    }
    if (i < 200*16*512) {             // fc nibble table
        int m = i & 511, idx = (i >> 9) & 15, gg = i >> 13;
        long long s = 0;
#pragma unroll
        for (int j = 0; j < 4; j++)
            if ((idx >> j) & 1) s += g_wfcll[(4*gg + j)*512 + m];
        g_tbf[i] = s;
    }
}

// ---------------- K2: ALL 64 timesteps, persistent, conv1 FUSED -------------
// grid 128, block 1024 = two independent 512-thread halves (one sample each),
// synced by named barriers. Per t and half:
//   A0: stage x[t][b] -> smem
//   A:  conv1 (packed f32x2 limb accumulation, identical to R13 k_conv1_all)
//       + LIF0 (state in gmem/L2) + 2x2 pool -> s_in
//   B:  conv2 via exact int64 byte tables + LIF1 + pool -> s_sp1
//   C:  FC via exact int64 nibble tables + LIF2 -> s_z2
//   D:  readout (exact int64) + LI -> volt
// Static smem ~44KB keeps L1D large for the conv2/fc tables (R16 lesson).
__global__ __launch_bounds__(1024) void k_steps(
    const float* __restrict__ x,  const float* __restrict__ w1,
    const float* __restrict__ b1, const float* __restrict__ b2,
    const float* __restrict__ b_fc, float* __restrict__ volt)
{
    __shared__ float s_in[2][2880];
    __shared__ int   s_off[512];
    __shared__ float s_sp1[2][800];
    __shared__ float s_z2[2][512];
    __shared__ float s_x[2][784];
    __shared__ float s_w1[500];
    __shared__ float s_b1[20];

    int half = threadIdx.x >> 9;
    int tid  = threadIdx.x & 511;
    int b    = blockIdx.x*2 + half;
    int lane = tid & 31;
    int warp = tid >> 5;              // 0..15 within half
    int barid = 1 + half;

    if (threadIdx.x < 512) {
        int tt = (threadIdx.x < 500) ? (int)threadIdx.x : 0;
        int ci = tt / 25, k = tt % 25;
        s_off[threadIdx.x] = ci*144 + (k/5)*12 + (k%5);
        if (threadIdx.x < 500) s_w1[threadIdx.x] = w1[threadIdx.x];
        if (threadIdx.x < 20)  s_b1[threadIdx.x] = b1[threadIdx.x];
    }

    int yp = warp >> 2, xq = warp & 3;
    int co = lane, co2 = lane + 32;
    float bias0 = __ldg(&b2[co]);
    float bias1 = (co2 < 50) ? __ldg(&b2[co2]) : 0.f;
    float biasf = (tid < 500) ? __ldg(&b_fc[tid]) : 0.f;
    float* v0p = g_v0 + b*11520;
    float* i0p = g_i0 + b*11520;

    const u64 SGN  = 0x8000000080000000ULL;
    const u64 M18  = pk2(48.0f, 48.0f);            // 1.5*2^5 -> grid 2^-18
    const u64 nM18 = pk2(-48.0f, -48.0f);

    __syncthreads();                  // s_off/s_w1/s_b1 visible

    for (int t = 0; t < TSTEPS; t++) {
        // ---- Phase A0: stage x[t][b] ----
        {
            const float* xp = x + ((size_t)t*BATCH + b)*784;
            for (int i = tid; i < 784; i += 512) s_x[half][i] = xp[i];
        }
        asm volatile("bar.sync %0, 512;" :: "r"(barid) : "memory");

        // ---- Phase A: conv1 + LIF0 + pool (fused; R13 limb arithmetic) ----
        for (int q = tid; q < 2880; q += 512) {
            int cch = q / 144, rr = q % 144;
            int r = rr / 12, xx = rr % 12;
            int y0 = 2*r, x0 = 2*xx;

            float in[6][6];
#pragma unroll
            for (int i = 0; i < 6; i++)
#pragma unroll
                for (int j = 0; j < 6; j++)
                    in[i][j] = s_x[half][(y0+i)*28 + x0 + j];

            u64 AhT = 0, FrT = 0, AhB = 0, FrB = 0;
            const float* wp = s_w1 + cch*25;
#pragma unroll
            for (int ki = 0; ki < 5; ki++)
#pragma unroll
                for (int kj = 0; kj < 5; kj++) {
                    float w = wp[ki*5 + kj];
                    u64 ww = pk2(w, w);
                    u64 aT = pk2(in[ki  ][kj], in[ki  ][kj+1]);
                    u64 aB = pk2(in[ki+1][kj], in[ki+1][kj+1]);
                    {
                        u64 t1 = fma2(aT, ww, M18);
                        u64 hf = add2(t1, nM18);
                        AhT = add2(AhT, hf);
                        u64 rr2 = fma2(aT, ww, hf ^ SGN);
                        FrT = add2(FrT, rr2);
                    }
                    {
                        u64 t1 = fma2(aB, ww, M18);
                        u64 hf = add2(t1, nM18);
                        AhB = add2(AhB, hf);
                        u64 rr2 = fma2(aB, ww, hf ^ SGN);
                        FrB = add2(FrB, rr2);
                    }
                }

            float bias = s_b1[cch];
            float ah0, ah1, fr0, fr1;
            upk2(AhT, ah0, ah1); upk2(FrT, fr0, fr1);
            float s00 = __fadd_rn(__fadd_rn(ah0, fr0), bias);
            float s01 = __fadd_rn(__fadd_rn(ah1, fr1), bias);
            upk2(AhB, ah0, ah1); upk2(FrB, fr0, fr1);
            float s10 = __fadd_rn(__fadd_rn(ah0, fr0), bias);
            float s11 = __fadd_rn(__fadd_rn(ah1, fr1), bias);

            int base = (cch*24 + y0)*24 + x0;
            float zmax = 0.f;
            {
                float2 v  = *(float2*)&v0p[base];
                float2 ii = *(float2*)&i0p[base];
                float z0, z1;
                lif_update(v.x, ii.x, s00, z0);
                lif_update(v.y, ii.y, s01, z1);
                *(float2*)&v0p[base] = v;
                *(float2*)&i0p[base] = ii;
                zmax = fmaxf(zmax, fmaxf(z0, z1));
            }
            {
                int idx = base + 24;
                float2 v  = *(float2*)&v0p[idx];
                float2 ii = *(float2*)&i0p[idx];
                float z0, z1;
                lif_update(v.x, ii.x, s10, z0);
                lif_update(v.y, ii.y, s11, z1);
                *(float2*)&v0p[idx] = v;
                *(float2*)&i0p[idx] = ii;
                zmax = fmaxf(zmax, fmaxf(z0, z1));
            }
            s_in[half][q] = zmax;
        }
        asm volatile("bar.sync %0, 512;" :: "r"(barid) : "memory");

        // ---- Phase B: conv2 + LIF1 + pool (byte tables, 8 terms/load) ----
        {
            float z0max = 0.f, z1max = 0.f;
#pragma unroll
            for (int sp = 0; sp < 4; sp++) {
                int dy = sp >> 1, dx = sp & 1;
                int y = 2*yp + dy, xx2 = 2*xq + dx;
                int base = y*12 + xx2;

                long long acc0 = 0, acc1 = 0;
#pragma unroll 1
                for (int ch = 0; ch < 16; ch++) {
                    float a = s_in[half][s_off[ch*32 + lane] + base];
                    unsigned msk = __ballot_sync(0xffffffffu, a != 0.f);
#pragma unroll
                    for (int j = 0; j < 4; j++) {
                        unsigned idx = (msk >> (8*j)) & 255u;
                        if (idx) {
                            const longlong2 wv = *(const longlong2*)
                                &g_tb2b[((ch*4 + j)*256 + idx)*64 + lane*2];
                            acc0 += wv.x;
                            acc1 += wv.y;
                        }
                    }
                }
                float inp0 = __fmul_rn(10.0f, __fadd_rn(fx2f(acc0), bias0));
                float inp1 = __fmul_rn(10.0f, __fadd_rn(fx2f(acc1), bias1));

                int sidx = (b*64 + y*8 + xx2)*64 + lane;
                float v0 = g_v1[sidx],      i0 = g_i1[sidx];
                float v1 = g_v1[sidx + 32], i1 = g_i1[sidx + 32];
                float z0, z1;
                lif_update(v0, i0, inp0, z0);
                lif_update(v1, i1, inp1, z1);
                g_v1[sidx] = v0;      g_i1[sidx] = i0;
                g_v1[sidx + 32] = v1; g_i1[sidx + 32] = i1;
                z0max = fmaxf(z0max, z0);
                z1max = fmaxf(z1max, z1);
            }
            int pos = yp*4 + xq;
            s_sp1[half][co*16 + pos] = z0max;
            if (co2 < 50) s_sp1[half][co2*16 + pos] = z1max;
        }
        asm volatile("bar.sync %0, 512;" :: "r"(barid) : "memory");

        // ---- Phase C: FC + LIF2 (nibble tables) ----
        {
            int m = tid;
            long long acc = 0;
#pragma unroll 1
            for (int ch = 0; ch < 25; ch++) {
                float a = s_sp1[half][ch*32 + lane];
                unsigned msk = __ballot_sync(0xffffffffu, a != 0.f);
#pragma unroll
                for (int j = 0; j < 8; j++) {
                    unsigned idx = (msk >> (4*j)) & 15u;
                    if (idx)
                        acc += __ldg(&g_tbf[((ch*8 + j)*16 + idx)*512 + m]);
                }
            }
            float inp = __fadd_rn(fx2f(acc), biasf);

            int sidx = b*512 + m;
            float v = g_v2[sidx], ii = g_i2[sidx];
            float z;
            lif_update(v, ii, inp, z);
            g_v2[sidx] = v;
            g_i2[sidx] = ii;
            s_z2[half][m] = (m < 500) ? z : 0.f;
        }
        asm volatile("bar.sync %0, 512;" :: "r"(barid) : "memory");

        // ---- Phase D: readout + LI ----
        if (warp < 10) {
            long long ao = 0;
            const long long* wr = g_woutll + warp*500;
#pragma unroll 1
            for (int j = lane; j < 500; j += 32)
                if (s_z2[half][j] != 0.f) ao += __ldg(wr + j);
#pragma unroll
            for (int off = 16; off; off >>= 1)
                ao += __shfl_xor_sync(0xffffffffu, ao, off);
            if (lane == 0) {
                float sum = fx2f(ao);
                int idx = b*10 + warp;
                float vo = g_vo[idx], io = g_io[idx];
                float vn = __fadd_rn(vo, __fmul_rn(LIF_BETA, __fsub_rn(io, vo)));
                g_vo[idx] = vn;
                g_io[idx] = __fadd_rn(__fmul_rn(LIF_IDEC, io), sum);
                volt[((size_t)t * BATCH + b)*10 + warp] = vn;
            }
        }
        asm volatile("bar.sync %0, 512;" :: "r"(barid) : "memory");
    }
}

// ---------------- launch (single stream, serial) -----------------------------
extern "C" void kernel_launch(void* const* d_in, const int* in_sizes, int n_in,
                              void* d_out, int out_size)
{
    const float* x     = (const float*)d_in[0];
    const float* w1    = (const float*)d_in[1];
    const float* b1    = (const float*)d_in[2];
    const float* w2    = (const float*)d_in[3];
    const float* b2    = (const float*)d_in[4];
    const float* w_fc  = (const float*)d_in[5];
    const float* b_fc  = (const float*)d_in[6];
    const float* w_out = (const float*)d_in[7];
    float* volt = (float*)d_out;

    zero_states<<<(BATCH*20*576 + 255)/256, 256>>>();
    prep_weights<<<(800*512 + 255)/256, 256>>>(w2, w_fc, w_out);
    prep_tables<<<(200*16*512 + 255)/256, 256>>>();

    k_steps<<<BATCH/2, 1024>>>(x, w1, b1, b2, b_fc, volt);
}